// round 4
// baseline (speedup 1.0000x reference)
#include <cuda_runtime.h>
#include <math.h>

#define NN 14000        // nodes
#define HD 256          // hidden dim
#define K1N 16
#define K2N 32
#define KT 48           // K1N + K2N
#define CC 7            // classes
#define BB 64           // bottleneck dim
#define MR 100000       // embed rows
#define PER_CLASS 2000  // NN / CC
#define EPSV 1e-8f

// ---------------- scratch (device globals; no allocation allowed) ----------------
__device__ float g_inputs[NN * HD];   // weighted_neighbors + ce
__device__ float g_ce[NN * HD];       // selfprompt rows
__device__ float g_hidden[NN * BB];   // elu(inputs @ W1 + b1)
__device__ float g_rawret[NN * HD];   // prompts + ce
__device__ float g_clsum[CC * HD];    // per-class sums
__device__ float g_ave[CC * HD];      // per-class means
__device__ float g_avenorm[CC];       // clamped norms of means

// ---------------- K0: zero class sums ----------------
__global__ void k0_zero() {
    int t = blockIdx.x * blockDim.x + threadIdx.x;
    if (t < CC * HD) g_clsum[t] = 0.f;
}

// ---------------- K1: neighbor attention ----------------
// one block per node, 256 threads (8 warps). Neighbor tile staged in smem,
// gathered exactly once per node. Warp-per-neighbor dot/norm reductions.
__global__ __launch_bounds__(256) void k1_attn(
    const float* __restrict__ embeds, const float* __restrict__ w_self,
    const float* __restrict__ w_n, const float* __restrict__ w_n2,
    const int* __restrict__ idx, const int* __restrict__ nbr,
    const int* __restrict__ nbr2)
{
    extern __shared__ float sm[];
    float* s_nb  = sm;                 // [KT][HD]
    float* s_ce  = s_nb + KT * HD;     // [HD]
    float* s_dot = s_ce + HD;          // [KT]
    float* s_nrm = s_dot + KT;         // [KT]
    float* s_w   = s_nrm + KT;         // [KT]
    float* s_red = s_w + KT;           // [8]
    int*   s_nbr = (int*)(s_red + 8);  // [KT]

    const int n    = blockIdx.x;
    const int tid  = threadIdx.x;
    const int lane = tid & 31;
    const int wid  = tid >> 5;

    // stage neighbor indices early (overlaps with ce compute)
    if (tid < K1N)      s_nbr[tid] = nbr[n * K1N + tid];
    else if (tid < KT)  s_nbr[tid] = nbr2[n * K2N + (tid - K1N)];

    const int center = idx[n];
    const float ce_h = w_self[tid] * embeds[(long)center * HD + tid];
    s_ce[tid] = ce_h;

    // block reduce ||ce||^2
    float v = ce_h * ce_h;
    #pragma unroll
    for (int o = 16; o > 0; o >>= 1) v += __shfl_xor_sync(0xffffffffu, v, o);
    if (lane == 0) s_red[wid] = v;
    __syncthreads();

    float cs = 0.f;
    #pragma unroll
    for (int i = 0; i < 8; i++) cs += s_red[i];
    const float cenorm = fmaxf(sqrtf(cs), EPSV);

    // gather + scale neighbors, compute per-neighbor dot & norm
    #pragma unroll
    for (int kk = 0; kk < KT / 8; kk++) {
        const int k   = wid + kk * 8;
        const int row = s_nbr[k];
        const float4* er = (const float4*)(embeds + (long)row * HD);
        const float4* wr = (const float4*)((k < K1N) ? w_n : w_n2);
        const float4* cr = (const float4*)s_ce;
        float4* nbp = (float4*)(s_nb + k * HD);
        float dot = 0.f, nr = 0.f;
        #pragma unroll
        for (int j = 0; j < 2; j++) {
            const int e = lane + j * 32;
            float4 x = er[e];
            float4 w4 = wr[e];
            float4 c4 = cr[e];
            float4 val;
            val.x = w4.x * x.x; val.y = w4.y * x.y;
            val.z = w4.z * x.z; val.w = w4.w * x.w;
            nbp[e] = val;
            dot += c4.x * val.x + c4.y * val.y + c4.z * val.z + c4.w * val.w;
            nr  += val.x * val.x + val.y * val.y + val.z * val.z + val.w * val.w;
        }
        #pragma unroll
        for (int o = 16; o > 0; o >>= 1) {
            dot += __shfl_xor_sync(0xffffffffu, dot, o);
            nr  += __shfl_xor_sync(0xffffffffu, nr, o);
        }
        if (lane == 0) { s_dot[k] = dot; s_nrm[k] = nr; }
    }
    __syncthreads();

    // softmax over 48 sims (warp 0, two elements per lane)
    if (wid == 0) {
        float s0 = s_dot[lane] / (cenorm * fmaxf(sqrtf(s_nrm[lane]), EPSV));
        float s1 = -1e30f;
        if (lane < KT - 32)
            s1 = s_dot[lane + 32] / (cenorm * fmaxf(sqrtf(s_nrm[lane + 32]), EPSV));
        float m = fmaxf(s0, s1);
        #pragma unroll
        for (int o = 16; o > 0; o >>= 1) m = fmaxf(m, __shfl_xor_sync(0xffffffffu, m, o));
        float e0 = __expf(s0 - m);
        float e1 = (lane < KT - 32) ? __expf(s1 - m) : 0.f;
        float ss = e0 + e1;
        #pragma unroll
        for (int o = 16; o > 0; o >>= 1) ss += __shfl_xor_sync(0xffffffffu, ss, o);
        const float inv = 1.f / ss;
        s_w[lane] = e0 * inv;
        if (lane < KT - 32) s_w[lane + 32] = e1 * inv;
    }
    __syncthreads();

    // weighted neighbor sum from smem tile
    float acc = 0.f;
    #pragma unroll
    for (int k = 0; k < KT; k++) acc += s_w[k] * s_nb[k * HD + tid];
    g_inputs[n * HD + tid] = acc + s_ce[tid];
    g_ce[n * HD + tid] = s_ce[tid];
}

// ---------------- K2: hidden = elu(inputs @ W1 + b1) ----------------
// tiled sgemm: 64x64 tile (BN=64 = full width), BK=32, 4x4 register tile
__global__ __launch_bounds__(256) void k2_gemm(
    const float* __restrict__ W1, const float* __restrict__ b1)
{
    __shared__ float s_A[64 * 36];  // [m][k], pad 32->36
    __shared__ float s_B[32 * 64];  // [k][b]
    const int tid = threadIdx.x;
    const int tx = tid & 15, ty = tid >> 4;
    const int row0 = blockIdx.x * 64;
    float acc[4][4] = {};

    for (int kk = 0; kk < HD; kk += 32) {
        {
            const int m = tid >> 3;     // 0..31
            const int kq = tid & 7;     // float4 slot 0..7
            #pragma unroll
            for (int p = 0; p < 2; p++) {
                const int mm = m + p * 32;
                const int row = row0 + mm;
                float4 a = (row < NN)
                    ? *(const float4*)(g_inputs + (long)row * HD + kk + kq * 4)
                    : make_float4(0.f, 0.f, 0.f, 0.f);
                *(float4*)(s_A + mm * 36 + kq * 4) = a;
            }
        }
        {
            const int b = tid & 63;
            const int kb = tid >> 6;    // 0..3
            #pragma unroll
            for (int p = 0; p < 8; p++) {
                const int k = kb + p * 4;
                s_B[k * 64 + b] = W1[(kk + k) * BB + b];
            }
        }
        __syncthreads();
        #pragma unroll
        for (int k = 0; k < 32; k++) {
            const float4 bf = *(const float4*)(s_B + k * 64 + tx * 4);
            const float a0 = s_A[(ty * 4 + 0) * 36 + k];
            const float a1 = s_A[(ty * 4 + 1) * 36 + k];
            const float a2 = s_A[(ty * 4 + 2) * 36 + k];
            const float a3 = s_A[(ty * 4 + 3) * 36 + k];
            acc[0][0] += a0 * bf.x; acc[0][1] += a0 * bf.y; acc[0][2] += a0 * bf.z; acc[0][3] += a0 * bf.w;
            acc[1][0] += a1 * bf.x; acc[1][1] += a1 * bf.y; acc[1][2] += a1 * bf.z; acc[1][3] += a1 * bf.w;
            acc[2][0] += a2 * bf.x; acc[2][1] += a2 * bf.y; acc[2][2] += a2 * bf.z; acc[2][3] += a2 * bf.w;
            acc[3][0] += a3 * bf.x; acc[3][1] += a3 * bf.y; acc[3][2] += a3 * bf.z; acc[3][3] += a3 * bf.w;
        }
        __syncthreads();
    }
    #pragma unroll
    for (int i = 0; i < 4; i++) {
        const int row = row0 + ty * 4 + i;
        if (row >= NN) continue;
        #pragma unroll
        for (int j = 0; j < 4; j++) {
            const int col = tx * 4 + j;
            float vv = acc[i][j] + b1[col];
            vv = (vv > 0.f) ? vv : expm1f(vv);   // elu
            g_hidden[row * BB + col] = vv;
        }
    }
}

// ---------------- K3: rawret = hidden @ W2 + b2 + ce ; class sums ----------------
__global__ __launch_bounds__(256) void k3_gemm(
    const float* __restrict__ W2, const float* __restrict__ b2,
    const int* __restrict__ labels)
{
    __shared__ float s_A[64 * 68];   // hidden tile [m][k], pad 64->68
    __shared__ float s_B[64 * 64];   // W2 chunk [k][c]
    __shared__ float s_cls[CC * 64]; // per-block class partial sums
    const int tid = threadIdx.x;
    const int tx = tid & 15, ty = tid >> 4;
    const int row0 = blockIdx.x * 64;
    const int col0 = blockIdx.y * 64;
    float acc[4][4] = {};

    // zero class partials
    for (int i = tid; i < CC * 64; i += 256) s_cls[i] = 0.f;

    // load A (hidden) tile: 64 rows x K=64
    {
        const int kq = tid & 15;    // float4 slot 0..15
        const int m = tid >> 4;     // 0..15
        #pragma unroll
        for (int p = 0; p < 4; p++) {
            const int mm = m + p * 16;
            const int row = row0 + mm;
            float4 a = (row < NN)
                ? *(const float4*)(g_hidden + (long)row * BB + kq * 4)
                : make_float4(0.f, 0.f, 0.f, 0.f);
            *(float4*)(s_A + mm * 68 + kq * 4) = a;
        }
    }
    // load B (W2 col chunk): K=64 x 64 cols
    {
        const int c = tid & 63;
        const int kb = tid >> 6;    // 0..3
        #pragma unroll
        for (int p = 0; p < 16; p++) {
            const int k = kb + p * 4;
            s_B[k * 64 + c] = W2[k * HD + col0 + c];
        }
    }
    __syncthreads();

    #pragma unroll
    for (int k = 0; k < 64; k++) {
        const float4 bf = *(const float4*)(s_B + k * 64 + tx * 4);
        const float a0 = s_A[(ty * 4 + 0) * 68 + k];
        const float a1 = s_A[(ty * 4 + 1) * 68 + k];
        const float a2 = s_A[(ty * 4 + 2) * 68 + k];
        const float a3 = s_A[(ty * 4 + 3) * 68 + k];
        acc[0][0] += a0 * bf.x; acc[0][1] += a0 * bf.y; acc[0][2] += a0 * bf.z; acc[0][3] += a0 * bf.w;
        acc[1][0] += a1 * bf.x; acc[1][1] += a1 * bf.y; acc[1][2] += a1 * bf.z; acc[1][3] += a1 * bf.w;
        acc[2][0] += a2 * bf.x; acc[2][1] += a2 * bf.y; acc[2][2] += a2 * bf.z; acc[2][3] += a2 * bf.w;
        acc[3][0] += a3 * bf.x; acc[3][1] += a3 * bf.y; acc[3][2] += a3 * bf.z; acc[3][3] += a3 * bf.w;
    }

    #pragma unroll
    for (int i = 0; i < 4; i++) {
        const int row = row0 + ty * 4 + i;
        if (row >= NN) continue;
        const int lb = labels[row];
        #pragma unroll
        for (int j = 0; j < 4; j++) {
            const int cl = tx * 4 + j;
            const int gcol = col0 + cl;
            const float vv = acc[i][j] + b2[gcol] + g_ce[(long)row * HD + gcol];
            g_rawret[(long)row * HD + gcol] = vv;
            atomicAdd(&s_cls[lb * 64 + cl], vv);
        }
    }
    __syncthreads();
    for (int i = tid; i < CC * 64; i += 256)
        atomicAdd(&g_clsum[(i >> 6) * HD + col0 + (i & 63)], s_cls[i]);
}

// ---------------- K4: class means + clamped norms ----------------
__global__ void k4_ave() {
    const int c = blockIdx.x, tid = threadIdx.x;
    const int lane = tid & 31, wid = tid >> 5;
    __shared__ float s_red[8];
    const float a = g_clsum[c * HD + tid] * (1.0f / PER_CLASS);
    g_ave[c * HD + tid] = a;
    float v = a * a;
    #pragma unroll
    for (int o = 16; o > 0; o >>= 1) v += __shfl_xor_sync(0xffffffffu, v, o);
    if (lane == 0) s_red[wid] = v;
    __syncthreads();
    if (tid == 0) {
        float t = 0.f;
        #pragma unroll
        for (int i = 0; i < 8; i++) t += s_red[i];
        g_avenorm[c] = fmaxf(sqrtf(t), EPSV);
    }
}

// ---------------- K5: per-node cos vs 7 means + softmax ----------------
__global__ __launch_bounds__(256) void k5_out(float* __restrict__ out) {
    __shared__ float s_ave[CC * HD];
    __shared__ float s_an[CC];
    const int tid = threadIdx.x, lane = tid & 31, wid = tid >> 5;
    for (int i = tid; i < CC * HD; i += 256) s_ave[i] = g_ave[i];
    if (tid < CC) s_an[tid] = g_avenorm[tid];
    __syncthreads();

    const int n = blockIdx.x * 8 + wid;   // grid = NN/8 exactly
    const float4* r = (const float4*)(g_rawret + (long)n * HD);
    const float4 x0 = r[lane], x1 = r[lane + 32];
    float nrm = x0.x * x0.x + x0.y * x0.y + x0.z * x0.z + x0.w * x0.w
              + x1.x * x1.x + x1.y * x1.y + x1.z * x1.z + x1.w * x1.w;
    float d[CC];
    #pragma unroll
    for (int c = 0; c < CC; c++) {
        const float4* av = (const float4*)(s_ave + c * HD);
        const float4 a0 = av[lane], a1 = av[lane + 32];
        d[c] = x0.x * a0.x + x0.y * a0.y + x0.z * a0.z + x0.w * a0.w
             + x1.x * a1.x + x1.y * a1.y + x1.z * a1.z + x1.w * a1.w;
    }
    #pragma unroll
    for (int o = 16; o > 0; o >>= 1) {
        nrm += __shfl_xor_sync(0xffffffffu, nrm, o);
        #pragma unroll
        for (int c = 0; c < CC; c++) d[c] += __shfl_xor_sync(0xffffffffu, d[c], o);
    }
    const float rn = fmaxf(sqrtf(nrm), EPSV);
    float mx = -1e30f;
    float sim[CC];
    #pragma unroll
    for (int c = 0; c < CC; c++) {
        sim[c] = d[c] / (rn * s_an[c]);
        mx = fmaxf(mx, sim[c]);
    }
    float sum = 0.f;
    #pragma unroll
    for (int c = 0; c < CC; c++) { sim[c] = __expf(sim[c] - mx); sum += sim[c]; }
    const float inv = 1.f / sum;
    #pragma unroll
    for (int c = 0; c < CC; c++)
        if (lane == c) out[n * CC + c] = sim[c] * inv;
}

// ---------------- launch ----------------
#define SMEM_K1 ((KT * HD + HD + 3 * KT + 8) * 4 + KT * 4)

extern "C" void kernel_launch(void* const* d_in, const int* in_sizes, int n_in,
                              void* d_out, int out_size)
{
    const float* embeds = (const float*)d_in[0];
    const float* w_self = (const float*)d_in[1];
    const float* w_n    = (const float*)d_in[2];
    const float* w_n2   = (const float*)d_in[3];
    const float* W1     = (const float*)d_in[4];
    const float* b1     = (const float*)d_in[5];
    const float* W2     = (const float*)d_in[6];
    const float* b2     = (const float*)d_in[7];
    const int* idx      = (const int*)d_in[8];
    const int* nbr      = (const int*)d_in[9];
    const int* nbr2     = (const int*)d_in[10];
    const int* labels   = (const int*)d_in[11];
    float* out = (float*)d_out;

    cudaFuncSetAttribute(k1_attn, cudaFuncAttributeMaxDynamicSharedMemorySize, SMEM_K1);

    k0_zero<<<CC, 256>>>();
    k1_attn<<<NN, 256, SMEM_K1>>>(embeds, w_self, w_n, w_n2, idx, nbr, nbr2);
    k2_gemm<<<(NN + 63) / 64, 256>>>(W1, b1);
    k3_gemm<<<dim3((NN + 63) / 64, HD / 64), 256>>>(W2, b2, labels);
    k4_ave<<<CC, 256>>>();
    k5_out<<<NN / 8, 256>>>(out);
}

// round 9
// speedup vs baseline: 1.0411x; 1.0411x over previous
#include <cuda_runtime.h>
#include <math.h>

#define NN 14000        // nodes
#define HD 256          // hidden dim
#define K1N 16
#define K2N 32
#define KT 48           // K1N + K2N
#define CC 7            // classes
#define BB 64           // bottleneck dim
#define MR 100000       // embed rows
#define PER_CLASS 2000  // NN / CC
#define EPSV 1e-8f

// ---------------- scratch (device globals; no allocation allowed) ----------------
__device__ float g_inputs[NN * HD];   // weighted_neighbors + ce
__device__ float g_ce[NN * HD];       // selfprompt rows
__device__ float g_hidden[NN * BB];   // elu(inputs @ W1 + b1)
__device__ float g_rawret[NN * HD];   // prompts + ce
__device__ float g_clsum[CC * HD];    // per-class sums
__device__ float g_ave[CC * HD];      // per-class means
__device__ float g_avenorm[CC];       // clamped norms of means
__device__ float g_nrm1[MR];          // clamped ||w_n  * embeds[r]||
__device__ float g_nrm2[MR];          // clamped ||w_n2 * embeds[r]||

// ---------------- K_pre: per-row scaled norms (also warms L2 with embeds) ----------
__global__ __launch_bounds__(256) void k_pre(
    const float* __restrict__ embeds, const float* __restrict__ w_n,
    const float* __restrict__ w_n2)
{
    const int tid = threadIdx.x, lane = tid & 31, wid = tid >> 5;
    const int r = blockIdx.x * 8 + wid;           // MR/8 blocks exactly
    const float4* er  = (const float4*)(embeds + (long)r * HD);
    const float4* wn  = (const float4*)w_n;
    const float4* wn2 = (const float4*)w_n2;
    float s1 = 0.f, s2 = 0.f;
    #pragma unroll
    for (int j = 0; j < 2; j++) {
        const float4 e = er[lane + 32 * j];
        const float4 a = wn[lane + 32 * j];
        const float4 b = wn2[lane + 32 * j];
        float vx = a.x * e.x, vy = a.y * e.y, vz = a.z * e.z, vw = a.w * e.w;
        s1 += vx * vx + vy * vy + vz * vz + vw * vw;
        vx = b.x * e.x; vy = b.y * e.y; vz = b.z * e.z; vw = b.w * e.w;
        s2 += vx * vx + vy * vy + vz * vz + vw * vw;
    }
    #pragma unroll
    for (int o = 16; o > 0; o >>= 1) {
        s1 += __shfl_xor_sync(0xffffffffu, s1, o);
        s2 += __shfl_xor_sync(0xffffffffu, s2, o);
    }
    if (lane == 0) {
        g_nrm1[r] = fmaxf(sqrtf(s1), EPSV);
        g_nrm2[r] = fmaxf(sqrtf(s2), EPSV);
    }
}

// ---------------- K0: zero class sums ----------------
__global__ void k0_zero() {
    int t = blockIdx.x * blockDim.x + threadIdx.x;
    if (t < CC * HD) g_clsum[t] = 0.f;
}

// ---------------- K1: neighbor attention (cp.async gather, factored weights) -------
__global__ __launch_bounds__(256) void k1_attn(
    const float* __restrict__ embeds, const float* __restrict__ w_self,
    const float* __restrict__ w_n, const float* __restrict__ w_n2,
    const int* __restrict__ idx, const int* __restrict__ nbr,
    const int* __restrict__ nbr2)
{
    extern __shared__ float sm[];
    float* s_raw = sm;                    // [KT][HD] raw embed rows
    float* s_c1  = s_raw + KT * HD;       // ce * w_n
    float* s_c2  = s_c1 + HD;             // ce * w_n2
    float* s_sim = s_c2 + HD;             // [KT]
    float* s_w   = s_sim + KT;            // [KT]
    float* s_nrm = s_w + KT;              // [KT] precomputed clamped norms
    float* s_red = s_nrm + KT;            // [8]

    const int n = blockIdx.x, tid = threadIdx.x;
    const int lane = tid & 31, wid = tid >> 5;

    // Issue all gathers immediately: 12 x 16B cp.async per thread.
    {
        const int kbase = tid >> 6;       // 0..3
        const int slot  = tid & 63;       // float4 slot within a row
        #pragma unroll
        for (int i = 0; i < 12; i++) {
            const int k = kbase + i * 4;  // covers 0..47
            const int row = (i < 4) ? nbr[n * K1N + k] : nbr2[n * K2N + (k - K1N)];
            const float* src = embeds + (long)row * HD + slot * 4;
            const unsigned dst =
                (unsigned)__cvta_generic_to_shared(s_raw + k * HD + slot * 4);
            asm volatile("cp.async.cg.shared.global [%0], [%1], 16;\n"
                         :: "r"(dst), "l"(src));
        }
        asm volatile("cp.async.commit_group;\n" ::: "memory");
    }

    // Overlap: center row + factored dot vectors + neighbor norms.
    const int center = idx[n];
    const float e    = embeds[(long)center * HD + tid];
    const float wn   = w_n[tid], wn2v = w_n2[tid];
    const float ce   = w_self[tid] * e;
    s_c1[tid] = ce * wn;
    s_c2[tid] = ce * wn2v;

    if (tid < KT) {
        const int r = (tid < K1N) ? nbr[n * K1N + tid] : nbr2[n * K2N + tid - K1N];
        s_nrm[tid] = (tid < K1N) ? g_nrm1[r] : g_nrm2[r];
    }

    float v = ce * ce;
    #pragma unroll
    for (int o = 16; o > 0; o >>= 1) v += __shfl_xor_sync(0xffffffffu, v, o);
    if (lane == 0) s_red[wid] = v;

    asm volatile("cp.async.wait_group 0;\n" ::: "memory");
    __syncthreads();

    float cs = 0.f;
    #pragma unroll
    for (int i = 0; i < 8; i++) cs += s_red[i];
    const float cenorm = fmaxf(sqrtf(cs), EPSV);

    // Per-warp dot products from smem tile (6 neighbors per warp).
    #pragma unroll
    for (int kk = 0; kk < 6; kk++) {
        const int k = wid + kk * 8;       // kk<2 => k<16 (1-hop)
        const float4* rp  = (const float4*)(s_raw + k * HD);
        const float4* cpv = (const float4*)((kk < 2) ? s_c1 : s_c2);
        float dot = 0.f;
        #pragma unroll
        for (int j = 0; j < 2; j++) {
            const float4 x = rp[lane + 32 * j];
            const float4 c = cpv[lane + 32 * j];
            dot += c.x * x.x + c.y * x.y + c.z * x.z + c.w * x.w;
        }
        #pragma unroll
        for (int o = 16; o > 0; o >>= 1) dot += __shfl_xor_sync(0xffffffffu, dot, o);
        if (lane == 0) s_sim[k] = dot / (cenorm * s_nrm[k]);
    }
    __syncthreads();

    // softmax over 48 sims (warp 0)
    if (wid == 0) {
        const float s0 = s_sim[lane];
        const float s1 = (lane < KT - 32) ? s_sim[lane + 32] : -1e30f;
        float m = fmaxf(s0, s1);
        #pragma unroll
        for (int o = 16; o > 0; o >>= 1) m = fmaxf(m, __shfl_xor_sync(0xffffffffu, m, o));
        const float e0 = __expf(s0 - m);
        const float e1 = (lane < KT - 32) ? __expf(s1 - m) : 0.f;
        float ss = e0 + e1;
        #pragma unroll
        for (int o = 16; o > 0; o >>= 1) ss += __shfl_xor_sync(0xffffffffu, ss, o);
        const float inv = 1.f / ss;
        s_w[lane] = e0 * inv;
        if (lane < KT - 32) s_w[lane + 32] = e1 * inv;
    }
    __syncthreads();

    // Weighted sum of RAW rows per hop group, then apply w_n/w_n2 once.
    float acc1 = 0.f, acc2 = 0.f;
    #pragma unroll
    for (int k = 0; k < K1N; k++) acc1 += s_w[k] * s_raw[k * HD + tid];
    #pragma unroll
    for (int k = K1N; k < KT; k++) acc2 += s_w[k] * s_raw[k * HD + tid];
    g_inputs[(long)n * HD + tid] = wn * acc1 + wn2v * acc2 + ce;
    g_ce[(long)n * HD + tid] = ce;
}

// ---------------- K2: hidden = elu(inputs @ W1 + b1) ----------------
// 32(m) x 64(n) tile, BK=32, 128 threads, transposed-A smem for LDS.128 frags
__global__ __launch_bounds__(128) void k2_gemm(
    const float* __restrict__ W1, const float* __restrict__ b1)
{
    __shared__ float s_At[32 * 36];   // [k][m], pad 36 (16B aligned rows)
    __shared__ float s_B[32 * 64];    // [k][b]
    const int tid = threadIdx.x;
    const int tx = tid & 15, ty = tid >> 4;   // ty 0..7
    const int row0 = blockIdx.x * 32;
    float acc[4][4] = {};

    for (int kk = 0; kk < HD; kk += 32) {
        {
            const int kq = tid & 7;      // float4 slot
            const int m  = tid >> 3;     // 0..15
            #pragma unroll
            for (int p = 0; p < 2; p++) {
                const int mm = m + p * 16;
                const int row = row0 + mm;
                float4 a = (row < NN)
                    ? *(const float4*)(g_inputs + (long)row * HD + kk + kq * 4)
                    : make_float4(0.f, 0.f, 0.f, 0.f);
                s_At[(kq * 4 + 0) * 36 + mm] = a.x;
                s_At[(kq * 4 + 1) * 36 + mm] = a.y;
                s_At[(kq * 4 + 2) * 36 + mm] = a.z;
                s_At[(kq * 4 + 3) * 36 + mm] = a.w;
            }
        }
        {
            const int b = tid & 63;
            const int kb = tid >> 6;     // 0..1
            #pragma unroll
            for (int p = 0; p < 16; p++) {
                const int k = kb + p * 2;
                s_B[k * 64 + b] = W1[(kk + k) * BB + b];
            }
        }
        __syncthreads();
        #pragma unroll
        for (int k = 0; k < 32; k++) {
            const float4 a4 = *(const float4*)(s_At + k * 36 + ty * 4);
            const float4 b4 = *(const float4*)(s_B + k * 64 + tx * 4);
            acc[0][0] += a4.x * b4.x; acc[0][1] += a4.x * b4.y; acc[0][2] += a4.x * b4.z; acc[0][3] += a4.x * b4.w;
            acc[1][0] += a4.y * b4.x; acc[1][1] += a4.y * b4.y; acc[1][2] += a4.y * b4.z; acc[1][3] += a4.y * b4.w;
            acc[2][0] += a4.z * b4.x; acc[2][1] += a4.z * b4.y; acc[2][2] += a4.z * b4.z; acc[2][3] += a4.z * b4.w;
            acc[3][0] += a4.w * b4.x; acc[3][1] += a4.w * b4.y; acc[3][2] += a4.w * b4.z; acc[3][3] += a4.w * b4.w;
        }
        __syncthreads();
    }
    #pragma unroll
    for (int i = 0; i < 4; i++) {
        const int row = row0 + ty * 4 + i;
        if (row >= NN) continue;
        #pragma unroll
        for (int j = 0; j < 4; j++) {
            const int col = tx * 4 + j;
            float vv = acc[i][j] + b1[col];
            vv = (vv > 0.f) ? vv : expm1f(vv);   // elu
            g_hidden[row * BB + col] = vv;
        }
    }
}

// ---------------- K3: rawret = hidden @ W2 + b2 + ce ; class sums ----------------
// 32(m) x 64(n) tile, K=64 in one shot, 128 threads, transposed-A smem
__global__ __launch_bounds__(128) void k3_gemm(
    const float* __restrict__ W2, const float* __restrict__ b2,
    const int* __restrict__ labels)
{
    __shared__ float s_At[64 * 36];    // hidden transposed [k][m]
    __shared__ float s_B[64 * 64];     // W2 chunk [k][c]
    __shared__ float s_cls[CC * 64];   // per-block class partials
    const int tid = threadIdx.x;
    const int tx = tid & 15, ty = tid >> 4;
    const int row0 = blockIdx.x * 32;
    const int col0 = blockIdx.y * 64;

    for (int i = tid; i < CC * 64; i += 128) s_cls[i] = 0.f;

    {   // A: 32 rows x K=64, transposed
        const int kq = tid & 15;     // float4 slot
        const int m  = tid >> 4;     // 0..7
        #pragma unroll
        for (int p = 0; p < 4; p++) {
            const int mm = m + p * 8;
            const int row = row0 + mm;
            float4 a = (row < NN)
                ? *(const float4*)(g_hidden + (long)row * BB + kq * 4)
                : make_float4(0.f, 0.f, 0.f, 0.f);
            s_At[(kq * 4 + 0) * 36 + mm] = a.x;
            s_At[(kq * 4 + 1) * 36 + mm] = a.y;
            s_At[(kq * 4 + 2) * 36 + mm] = a.z;
            s_At[(kq * 4 + 3) * 36 + mm] = a.w;
        }
    }
    {   // B: K=64 x 64 cols
        const int c = tid & 63;
        const int kb = tid >> 6;     // 0..1
        #pragma unroll
        for (int p = 0; p < 32; p++) {
            const int k = kb + p * 2;
            s_B[k * 64 + c] = W2[k * HD + col0 + c];
        }
    }
    __syncthreads();

    float acc[4][4] = {};
    #pragma unroll
    for (int k = 0; k < 64; k++) {
        const float4 a4 = *(const float4*)(s_At + k * 36 + ty * 4);
        const float4 b4 = *(const float4*)(s_B + k * 64 + tx * 4);
        acc[0][0] += a4.x * b4.x; acc[0][1] += a4.x * b4.y; acc[0][2] += a4.x * b4.z; acc[0][3] += a4.x * b4.w;
        acc[1][0] += a4.y * b4.x; acc[1][1] += a4.y * b4.y; acc[1][2] += a4.y * b4.z; acc[1][3] += a4.y * b4.w;
        acc[2][0] += a4.z * b4.x; acc[2][1] += a4.z * b4.y; acc[2][2] += a4.z * b4.z; acc[2][3] += a4.z * b4.w;
        acc[3][0] += a4.w * b4.x; acc[3][1] += a4.w * b4.y; acc[3][2] += a4.w * b4.z; acc[3][3] += a4.w * b4.w;
    }

    #pragma unroll
    for (int i = 0; i < 4; i++) {
        const int row = row0 + ty * 4 + i;
        if (row >= NN) continue;
        const int lb = labels[row];
        #pragma unroll
        for (int j = 0; j < 4; j++) {
            const int cl = tx * 4 + j;
            const int gcol = col0 + cl;
            const float vv = acc[i][j] + b2[gcol] + g_ce[(long)row * HD + gcol];
            g_rawret[(long)row * HD + gcol] = vv;
            atomicAdd(&s_cls[lb * 64 + cl], vv);
        }
    }
    __syncthreads();
    for (int i = tid; i < CC * 64; i += 128)
        atomicAdd(&g_clsum[(i >> 6) * HD + col0 + (i & 63)], s_cls[i]);
}

// ---------------- K4: class means + clamped norms ----------------
__global__ void k4_ave() {
    const int c = blockIdx.x, tid = threadIdx.x;
    const int lane = tid & 31, wid = tid >> 5;
    __shared__ float s_red[8];
    const float a = g_clsum[c * HD + tid] * (1.0f / PER_CLASS);
    g_ave[c * HD + tid] = a;
    float v = a * a;
    #pragma unroll
    for (int o = 16; o > 0; o >>= 1) v += __shfl_xor_sync(0xffffffffu, v, o);
    if (lane == 0) s_red[wid] = v;
    __syncthreads();
    if (tid == 0) {
        float t = 0.f;
        #pragma unroll
        for (int i = 0; i < 8; i++) t += s_red[i];
        g_avenorm[c] = fmaxf(sqrtf(t), EPSV);
    }
}

// ---------------- K5: per-node cos vs 7 means + softmax ----------------
__global__ __launch_bounds__(256) void k5_out(float* __restrict__ out) {
    __shared__ float s_ave[CC * HD];
    __shared__ float s_an[CC];
    const int tid = threadIdx.x, lane = tid & 31, wid = tid >> 5;
    for (int i = tid; i < CC * HD; i += 256) s_ave[i] = g_ave[i];
    if (tid < CC) s_an[tid] = g_avenorm[tid];
    __syncthreads();

    const int n = blockIdx.x * 8 + wid;   // grid = NN/8 exactly
    const float4* r = (const float4*)(g_rawret + (long)n * HD);
    const float4 x0 = r[lane], x1 = r[lane + 32];
    float nrm = x0.x * x0.x + x0.y * x0.y + x0.z * x0.z + x0.w * x0.w
              + x1.x * x1.x + x1.y * x1.y + x1.z * x1.z + x1.w * x1.w;
    float d[CC];
    #pragma unroll
    for (int c = 0; c < CC; c++) {
        const float4* av = (const float4*)(s_ave + c * HD);
        const float4 a0 = av[lane], a1 = av[lane + 32];
        d[c] = x0.x * a0.x + x0.y * a0.y + x0.z * a0.z + x0.w * a0.w
             + x1.x * a1.x + x1.y * a1.y + x1.z * a1.z + x1.w * a1.w;
    }
    #pragma unroll
    for (int o = 16; o > 0; o >>= 1) {
        nrm += __shfl_xor_sync(0xffffffffu, nrm, o);
        #pragma unroll
        for (int c = 0; c < CC; c++) d[c] += __shfl_xor_sync(0xffffffffu, d[c], o);
    }
    const float rn = fmaxf(sqrtf(nrm), EPSV);
    float mx = -1e30f;
    float sim[CC];
    #pragma unroll
    for (int c = 0; c < CC; c++) {
        sim[c] = d[c] / (rn * s_an[c]);
        mx = fmaxf(mx, sim[c]);
    }
    float sum = 0.f;
    #pragma unroll
    for (int c = 0; c < CC; c++) { sim[c] = __expf(sim[c] - mx); sum += sim[c]; }
    const float inv = 1.f / sum;
    #pragma unroll
    for (int c = 0; c < CC; c++)
        if (lane == c) out[n * CC + c] = sim[c] * inv;
}

// ---------------- launch ----------------
#define SMEM_K1 ((KT * HD + 2 * HD + 3 * KT + 8) * 4)

extern "C" void kernel_launch(void* const* d_in, const int* in_sizes, int n_in,
                              void* d_out, int out_size)
{
    const float* embeds = (const float*)d_in[0];
    const float* w_self = (const float*)d_in[1];
    const float* w_n    = (const float*)d_in[2];
    const float* w_n2   = (const float*)d_in[3];
    const float* W1     = (const float*)d_in[4];
    const float* b1     = (const float*)d_in[5];
    const float* W2     = (const float*)d_in[6];
    const float* b2     = (const float*)d_in[7];
    const int* idx      = (const int*)d_in[8];
    const int* nbr      = (const int*)d_in[9];
    const int* nbr2     = (const int*)d_in[10];
    const int* labels   = (const int*)d_in[11];
    float* out = (float*)d_out;

    cudaFuncSetAttribute(k1_attn, cudaFuncAttributeMaxDynamicSharedMemorySize, SMEM_K1);

    k_pre<<<MR / 8, 256>>>(embeds, w_n, w_n2);
    k0_zero<<<CC, 256>>>();
    k1_attn<<<NN, 256, SMEM_K1>>>(embeds, w_self, w_n, w_n2, idx, nbr, nbr2);
    k2_gemm<<<(NN + 31) / 32, 128>>>(W1, b1);
    k3_gemm<<<dim3((NN + 31) / 32, HD / 64), 128>>>(W2, b2, labels);
    k4_ave<<<CC, 256>>>();
    k5_out<<<NN / 8, 256>>>(out);
}

// round 10
// speedup vs baseline: 1.0945x; 1.0513x over previous
#include <cuda_runtime.h>
#include <math.h>

#define NN 14000        // nodes
#define HD 256          // hidden dim
#define K1N 16
#define K2N 32
#define KT 48           // K1N + K2N
#define CC 7            // classes
#define BB 64           // bottleneck dim
#define MR 100000       // embed rows
#define PER_CLASS 2000  // NN / CC
#define EPSV 1e-8f

// ---------------- scratch (device globals; no allocation allowed) ----------------
__device__ float g_inputs[NN * HD];   // weighted_neighbors + ce
__device__ float g_ce[NN * HD];       // selfprompt rows
__device__ float g_rawret[NN * HD];   // prompts + ce
__device__ float g_clsum[CC * HD];    // per-class sums (atomics)

// ---------------- K1: neighbor attention (cp.async gather, inline norms) ----------
// one block per node, 256 threads. Also zeroes g_clsum (blocks 0..CC-1).
__global__ __launch_bounds__(256) void k1_attn(
    const float* __restrict__ embeds, const float* __restrict__ w_self,
    const float* __restrict__ w_n, const float* __restrict__ w_n2,
    const int* __restrict__ idx, const int* __restrict__ nbr,
    const int* __restrict__ nbr2)
{
    extern __shared__ float sm[];
    float* s_raw = sm;                    // [KT][HD] raw embed rows
    float* s_c1  = s_raw + KT * HD;       // ce * w_n
    float* s_c2  = s_c1 + HD;             // ce * w_n2
    float* s_q1  = s_c2 + HD;             // w_n^2
    float* s_q2  = s_q1 + HD;             // w_n2^2
    float* s_sim = s_q2 + HD;             // [KT]
    float* s_w   = s_sim + KT;            // [KT]
    float* s_red = s_w + KT;              // [8]

    const int n = blockIdx.x, tid = threadIdx.x;
    const int lane = tid & 31, wid = tid >> 5;

    // fold k0: zero class sums (executes before k23's atomics, same stream)
    if (n < CC) g_clsum[n * HD + tid] = 0.f;

    // Issue all gathers immediately: 12 x 16B cp.async per thread.
    {
        const int kbase = tid >> 6;       // 0..3
        const int slot  = tid & 63;       // float4 slot within a row
        #pragma unroll
        for (int i = 0; i < 12; i++) {
            const int k = kbase + i * 4;  // covers 0..47
            const int row = (i < 4) ? nbr[n * K1N + k] : nbr2[n * K2N + (k - K1N)];
            const float* src = embeds + (long)row * HD + slot * 4;
            const unsigned dst =
                (unsigned)__cvta_generic_to_shared(s_raw + k * HD + slot * 4);
            asm volatile("cp.async.cg.shared.global [%0], [%1], 16;\n"
                         :: "r"(dst), "l"(src));
        }
        asm volatile("cp.async.commit_group;\n" ::: "memory");
    }

    // Overlap: center row + factored dot vectors + squared weights.
    const int center = idx[n];
    const float e    = embeds[(long)center * HD + tid];
    const float wn   = w_n[tid], wn2v = w_n2[tid];
    const float ce   = w_self[tid] * e;
    s_c1[tid] = ce * wn;
    s_c2[tid] = ce * wn2v;
    s_q1[tid] = wn * wn;
    s_q2[tid] = wn2v * wn2v;

    float v = ce * ce;
    #pragma unroll
    for (int o = 16; o > 0; o >>= 1) v += __shfl_xor_sync(0xffffffffu, v, o);
    if (lane == 0) s_red[wid] = v;

    asm volatile("cp.async.wait_group 0;\n" ::: "memory");
    __syncthreads();

    float cs = 0.f;
    #pragma unroll
    for (int i = 0; i < 8; i++) cs += s_red[i];
    const float cenorm = fmaxf(sqrtf(cs), EPSV);

    // Per-warp dot + norm from smem tile (6 neighbors per warp).
    #pragma unroll
    for (int kk = 0; kk < 6; kk++) {
        const int k = wid + kk * 8;       // kk<2 => k<16 (1-hop)
        const float4* rp  = (const float4*)(s_raw + k * HD);
        const float4* cpv = (const float4*)((kk < 2) ? s_c1 : s_c2);
        const float4* qpv = (const float4*)((kk < 2) ? s_q1 : s_q2);
        float dot = 0.f, nr = 0.f;
        #pragma unroll
        for (int j = 0; j < 2; j++) {
            const float4 x = rp[lane + 32 * j];
            const float4 c = cpv[lane + 32 * j];
            const float4 q = qpv[lane + 32 * j];
            dot += c.x * x.x + c.y * x.y + c.z * x.z + c.w * x.w;
            nr  += q.x * x.x * x.x + q.y * x.y * x.y
                 + q.z * x.z * x.z + q.w * x.w * x.w;
        }
        #pragma unroll
        for (int o = 16; o > 0; o >>= 1) {
            dot += __shfl_xor_sync(0xffffffffu, dot, o);
            nr  += __shfl_xor_sync(0xffffffffu, nr, o);
        }
        if (lane == 0)
            s_sim[k] = dot / (cenorm * fmaxf(sqrtf(nr), EPSV));
    }
    __syncthreads();

    // softmax over 48 sims (warp 0)
    if (wid == 0) {
        const float s0 = s_sim[lane];
        const float s1 = (lane < KT - 32) ? s_sim[lane + 32] : -1e30f;
        float m = fmaxf(s0, s1);
        #pragma unroll
        for (int o = 16; o > 0; o >>= 1) m = fmaxf(m, __shfl_xor_sync(0xffffffffu, m, o));
        const float e0 = __expf(s0 - m);
        const float e1 = (lane < KT - 32) ? __expf(s1 - m) : 0.f;
        float ss = e0 + e1;
        #pragma unroll
        for (int o = 16; o > 0; o >>= 1) ss += __shfl_xor_sync(0xffffffffu, ss, o);
        const float inv = 1.f / ss;
        s_w[lane] = e0 * inv;
        if (lane < KT - 32) s_w[lane + 32] = e1 * inv;
    }
    __syncthreads();

    // Weighted sum of RAW rows per hop group, then apply w_n/w_n2 once.
    float acc1 = 0.f, acc2 = 0.f;
    #pragma unroll
    for (int k = 0; k < K1N; k++) acc1 += s_w[k] * s_raw[k * HD + tid];
    #pragma unroll
    for (int k = K1N; k < KT; k++) acc2 += s_w[k] * s_raw[k * HD + tid];
    g_inputs[(long)n * HD + tid] = wn * acc1 + wn2v * acc2 + ce;
    g_ce[(long)n * HD + tid] = ce;
}

// ---------------- K23: fused adapter ----------------
// Phase 1: hidden = elu(inputs[32xHD] @ W1 + b1)  (kept in smem, transposed)
// Phase 2: rawret = hidden @ W2 + b2 + ce, class sums via smem atomics.
// 128 threads, 32-row tile. smem ~32KB -> ~7 blocks/SM.
__global__ __launch_bounds__(128) void k23_fused(
    const float* __restrict__ W1, const float* __restrict__ b1,
    const float* __restrict__ W2, const float* __restrict__ b2,
    const int* __restrict__ labels)
{
    __shared__ float s_At[32 * 36];    // phase1 A chunk [k][m], pad 36
    __shared__ float s_B[64 * 64];     // W1 chunk (32x64) / W2 chunk (64x64)
    __shared__ float s_ht[64 * 36];    // hidden transposed [k=64][m], pad 36
    __shared__ float s_cls[CC * 64];   // per-block per-chunk class partials
    const int tid = threadIdx.x;
    const int tx = tid & 15, ty = tid >> 4;   // ty 0..7
    const int row0 = blockIdx.x * 32;

    for (int i = tid; i < CC * 64; i += 128) s_cls[i] = 0.f;

    // ---- phase 1: 32xHD @ HDx64 ----
    float acc[4][4] = {};
    for (int kk = 0; kk < HD; kk += 32) {
        {
            const int kq = tid & 7;      // float4 slot
            const int m  = tid >> 3;     // 0..15
            #pragma unroll
            for (int p = 0; p < 2; p++) {
                const int mm = m + p * 16;
                const int row = row0 + mm;
                float4 a = (row < NN)
                    ? *(const float4*)(g_inputs + (long)row * HD + kk + kq * 4)
                    : make_float4(0.f, 0.f, 0.f, 0.f);
                s_At[(kq * 4 + 0) * 36 + mm] = a.x;
                s_At[(kq * 4 + 1) * 36 + mm] = a.y;
                s_At[(kq * 4 + 2) * 36 + mm] = a.z;
                s_At[(kq * 4 + 3) * 36 + mm] = a.w;
            }
        }
        {
            const int b = tid & 63;
            const int kb = tid >> 6;     // 0..1
            #pragma unroll
            for (int p = 0; p < 16; p++) {
                const int k = kb + p * 2;
                s_B[k * 64 + b] = W1[(kk + k) * BB + b];
            }
        }
        __syncthreads();
        #pragma unroll
        for (int k = 0; k < 32; k++) {
            const float4 a4 = *(const float4*)(s_At + k * 36 + ty * 4);
            const float4 b4 = *(const float4*)(s_B + k * 64 + tx * 4);
            acc[0][0] += a4.x * b4.x; acc[0][1] += a4.x * b4.y; acc[0][2] += a4.x * b4.z; acc[0][3] += a4.x * b4.w;
            acc[1][0] += a4.y * b4.x; acc[1][1] += a4.y * b4.y; acc[1][2] += a4.y * b4.z; acc[1][3] += a4.y * b4.w;
            acc[2][0] += a4.z * b4.x; acc[2][1] += a4.z * b4.y; acc[2][2] += a4.z * b4.z; acc[2][3] += a4.z * b4.w;
            acc[3][0] += a4.w * b4.x; acc[3][1] += a4.w * b4.y; acc[3][2] += a4.w * b4.z; acc[3][3] += a4.w * b4.w;
        }
        __syncthreads();
    }
    // elu + stash hidden transposed in smem: s_ht[col][m]
    #pragma unroll
    for (int i = 0; i < 4; i++) {
        const int mm = ty * 4 + i;
        #pragma unroll
        for (int j = 0; j < 4; j++) {
            const int col = tx * 4 + j;
            float vv = acc[i][j] + b1[col];
            vv = (vv > 0.f) ? vv : expm1f(vv);   // elu
            s_ht[col * 36 + mm] = vv;
        }
    }
    __syncthreads();

    // ---- phase 2: 32x64 @ 64xHD in 4 col-chunks ----
    for (int ccn = 0; ccn < 4; ccn++) {
        const int col0 = ccn * 64;
        {   // load W2 chunk [64][64]
            const int c = tid & 63;
            const int kb = tid >> 6;     // 0..1
            #pragma unroll
            for (int p = 0; p < 32; p++) {
                const int k = kb + p * 2;
                s_B[k * 64 + c] = W2[k * HD + col0 + c];
            }
        }
        __syncthreads();

        float a2[4][4] = {};
        #pragma unroll
        for (int k = 0; k < 64; k++) {
            const float4 a4 = *(const float4*)(s_ht + k * 36 + ty * 4);
            const float4 b4 = *(const float4*)(s_B + k * 64 + tx * 4);
            a2[0][0] += a4.x * b4.x; a2[0][1] += a4.x * b4.y; a2[0][2] += a4.x * b4.z; a2[0][3] += a4.x * b4.w;
            a2[1][0] += a4.y * b4.x; a2[1][1] += a4.y * b4.y; a2[1][2] += a4.y * b4.z; a2[1][3] += a4.y * b4.w;
            a2[2][0] += a4.z * b4.x; a2[2][1] += a4.z * b4.y; a2[2][2] += a4.z * b4.z; a2[2][3] += a4.z * b4.w;
            a2[3][0] += a4.w * b4.x; a2[3][1] += a4.w * b4.y; a2[3][2] += a4.w * b4.z; a2[3][3] += a4.w * b4.w;
        }

        #pragma unroll
        for (int i = 0; i < 4; i++) {
            const int row = row0 + ty * 4 + i;
            if (row >= NN) continue;
            const int lb = labels[row];
            #pragma unroll
            for (int j = 0; j < 4; j++) {
                const int cl = tx * 4 + j;
                const int gcol = col0 + cl;
                const float vv = a2[i][j] + b2[gcol] + g_ce[(long)row * HD + gcol];
                g_rawret[(long)row * HD + gcol] = vv;
                atomicAdd(&s_cls[lb * 64 + cl], vv);
            }
        }
        __syncthreads();
        for (int i = tid; i < CC * 64; i += 128) {
            atomicAdd(&g_clsum[(i >> 6) * HD + col0 + (i & 63)], s_cls[i]);
            s_cls[i] = 0.f;
        }
        __syncthreads();
    }
}

// ---------------- K5: per-node cos vs 7 class means + softmax (folds k4) ---------
__global__ __launch_bounds__(256) void k5_out(float* __restrict__ out) {
    __shared__ float s_ave[CC * HD];
    __shared__ float s_an[CC];
    const int tid = threadIdx.x, lane = tid & 31, wid = tid >> 5;
    for (int i = tid; i < CC * HD; i += 256)
        s_ave[i] = g_clsum[i] * (1.0f / PER_CLASS);
    __syncthreads();
    // warp w computes class w's clamped norm (w < CC)
    if (wid < CC) {
        float v = 0.f;
        #pragma unroll
        for (int t = 0; t < HD / 32; t++) {
            const float a = s_ave[wid * HD + lane + 32 * t];
            v += a * a;
        }
        #pragma unroll
        for (int o = 16; o > 0; o >>= 1) v += __shfl_xor_sync(0xffffffffu, v, o);
        if (lane == 0) s_an[wid] = fmaxf(sqrtf(v), EPSV);
    }
    __syncthreads();

    const int n = blockIdx.x * 8 + wid;   // grid = NN/8 exactly
    const float4* r = (const float4*)(g_rawret + (long)n * HD);
    const float4 x0 = r[lane], x1 = r[lane + 32];
    float nrm = x0.x * x0.x + x0.y * x0.y + x0.z * x0.z + x0.w * x0.w
              + x1.x * x1.x + x1.y * x1.y + x1.z * x1.z + x1.w * x1.w;
    float d[CC];
    #pragma unroll
    for (int c = 0; c < CC; c++) {
        const float4* av = (const float4*)(s_ave + c * HD);
        const float4 a0 = av[lane], a1 = av[lane + 32];
        d[c] = x0.x * a0.x + x0.y * a0.y + x0.z * a0.z + x0.w * a0.w
             + x1.x * a1.x + x1.y * a1.y + x1.z * a1.z + x1.w * a1.w;
    }
    #pragma unroll
    for (int o = 16; o > 0; o >>= 1) {
        nrm += __shfl_xor_sync(0xffffffffu, nrm, o);
        #pragma unroll
        for (int c = 0; c < CC; c++) d[c] += __shfl_xor_sync(0xffffffffu, d[c], o);
    }
    const float rn = fmaxf(sqrtf(nrm), EPSV);
    float mx = -1e30f;
    float sim[CC];
    #pragma unroll
    for (int c = 0; c < CC; c++) {
        sim[c] = d[c] / (rn * s_an[c]);
        mx = fmaxf(mx, sim[c]);
    }
    float sum = 0.f;
    #pragma unroll
    for (int c = 0; c < CC; c++) { sim[c] = __expf(sim[c] - mx); sum += sim[c]; }
    const float inv = 1.f / sum;
    #pragma unroll
    for (int c = 0; c < CC; c++)
        if (lane == c) out[n * CC + c] = sim[c] * inv;
}

// ---------------- launch ----------------
#define SMEM_K1 ((KT * HD + 4 * HD + 2 * KT + 8) * 4)

extern "C" void kernel_launch(void* const* d_in, const int* in_sizes, int n_in,
                              void* d_out, int out_size)
{
    const float* embeds = (const float*)d_in[0];
    const float* w_self = (const float*)d_in[1];
    const float* w_n    = (const float*)d_in[2];
    const float* w_n2   = (const float*)d_in[3];
    const float* W1     = (const float*)d_in[4];
    const float* b1     = (const float*)d_in[5];
    const float* W2     = (const float*)d_in[6];
    const float* b2     = (const float*)d_in[7];
    const int* idx      = (const int*)d_in[8];
    const int* nbr      = (const int*)d_in[9];
    const int* nbr2     = (const int*)d_in[10];
    const int* labels   = (const int*)d_in[11];
    float* out = (float*)d_out;

    cudaFuncSetAttribute(k1_attn, cudaFuncAttributeMaxDynamicSharedMemorySize, SMEM_K1);

    k1_attn<<<NN, 256, SMEM_K1>>>(embeds, w_self, w_n, w_n2, idx, nbr, nbr2);
    k23_fused<<<(NN + 31) / 32, 128>>>(W1, b1, W2, b2, labels);
    k5_out<<<NN / 8, 256>>>(out);
}

// round 12
// speedup vs baseline: 1.1100x; 1.0141x over previous
#include <cuda_runtime.h>
#include <math.h>

#define NN 14000        // nodes
#define HD 256          // hidden dim
#define K1N 16
#define K2N 32
#define KT 48           // K1N + K2N
#define CC 7            // classes
#define BB 64           // bottleneck dim
#define MR 100000       // embed rows
#define PER_CLASS 2000  // NN / CC
#define EPSV 1e-8f

// ---------------- scratch (device globals; no allocation allowed) ----------------
__device__ float g_inputs[NN * HD];   // weighted_neighbors + ce
__device__ float g_ce[NN * HD];       // selfprompt rows
__device__ float g_rawret[NN * HD];   // prompts + ce
__device__ float g_clsum[CC * HD];    // per-class sums (atomics)

// ---------------- K1: neighbor attention ----------------
// one block per node, 256 threads. Register-cached ce/w slices; x is the only
// per-neighbor smem read in the dot loop. Split cp.async groups overlap the
// second gather half with the first half's dots. Also zeroes g_clsum.
__global__ __launch_bounds__(256, 4) void k1_attn(
    const float* __restrict__ embeds, const float* __restrict__ w_self,
    const float* __restrict__ w_n, const float* __restrict__ w_n2,
    const int* __restrict__ idx, const int* __restrict__ nbr,
    const int* __restrict__ nbr2)
{
    extern __shared__ float sm[];
    float* s_raw = sm;                    // [KT][HD] raw embed rows
    float* s_ce  = s_raw + KT * HD;       // ce (w_self * center)
    float* s_wn  = s_ce + HD;             // w_n
    float* s_wn2 = s_wn + HD;             // w_n2
    float* s_sim = s_wn2 + HD;            // [KT]
    float* s_w   = s_sim + KT;            // [KT]
    float* s_red = s_w + KT;              // [8]

    const int n = blockIdx.x, tid = threadIdx.x;
    const int lane = tid & 31, wid = tid >> 5;

    // fold k0: zero class sums (runs before k23's atomics, same stream)
    if (n < CC) g_clsum[n * HD + tid] = 0.f;

    // Issue gathers as TWO commit groups: A = neighbors 0..23, B = 24..47.
    {
        const int kbase = tid >> 6;       // 0..3
        const int slot  = tid & 63;       // float4 slot within a row
        #pragma unroll
        for (int i = 0; i < 6; i++) {     // group A: k in 0..23
            const int k = kbase + i * 4;
            const int row = (i < 4) ? nbr[n * K1N + k] : nbr2[n * K2N + (k - K1N)];
            const float* src = embeds + (long)row * HD + slot * 4;
            const unsigned dst =
                (unsigned)__cvta_generic_to_shared(s_raw + k * HD + slot * 4);
            asm volatile("cp.async.cg.shared.global [%0], [%1], 16;\n"
                         :: "r"(dst), "l"(src));
        }
        asm volatile("cp.async.commit_group;\n" ::: "memory");
        #pragma unroll
        for (int i = 6; i < 12; i++) {    // group B: k in 24..47
            const int k = kbase + i * 4;
            const int row = nbr2[n * K2N + (k - K1N)];
            const float* src = embeds + (long)row * HD + slot * 4;
            const unsigned dst =
                (unsigned)__cvta_generic_to_shared(s_raw + k * HD + slot * 4);
            asm volatile("cp.async.cg.shared.global [%0], [%1], 16;\n"
                         :: "r"(dst), "l"(src));
        }
        asm volatile("cp.async.commit_group;\n" ::: "memory");
    }

    // Overlap: center row, base vectors to smem, ce norm reduction.
    const int center = idx[n];
    const float e    = embeds[(long)center * HD + tid];
    const float wn   = w_n[tid], wn2v = w_n2[tid];
    const float ce   = w_self[tid] * e;
    s_ce[tid]  = ce;
    s_wn[tid]  = wn;
    s_wn2[tid] = wn2v;

    float v = ce * ce;
    #pragma unroll
    for (int o = 16; o > 0; o >>= 1) v += __shfl_xor_sync(0xffffffffu, v, o);
    if (lane == 0) s_red[wid] = v;

    // Wait for group A only (group B still in flight).
    asm volatile("cp.async.wait_group 1;\n" ::: "memory");
    __syncthreads();

    float cs = 0.f;
    #pragma unroll
    for (int i = 0; i < 8; i++) cs += s_red[i];
    const float cenorm = fmaxf(sqrtf(cs), EPSV);

    // Hoist per-lane invariant slices into registers (read smem ONCE).
    const float4* ce4  = (const float4*)s_ce;
    const float4* w14  = (const float4*)s_wn;
    const float4* w24  = (const float4*)s_wn2;
    const float4 ce_a = ce4[lane], ce_b = ce4[lane + 32];
    const float4 w1_a = w14[lane], w1_b = w14[lane + 32];
    const float4 w2_a = w24[lane], w2_b = w24[lane + 32];

    // Dot + norm: y = w .* x ; dot = ce.y ; nr = y.y  (x is sole smem read)
    #pragma unroll
    for (int kk = 0; kk < 6; kk++) {
        if (kk == 3) {   // neighbors >= 24 need group B
            asm volatile("cp.async.wait_group 0;\n" ::: "memory");
            __syncthreads();
        }
        const int k = wid + kk * 8;       // kk<2 => k<16 (1-hop)
        const float4 wa = (kk < 2) ? w1_a : w2_a;
        const float4 wb = (kk < 2) ? w1_b : w2_b;
        const float4* rp = (const float4*)(s_raw + k * HD);
        const float4 xa = rp[lane], xb = rp[lane + 32];
        float dot, nr;
        {
            const float y0 = wa.x * xa.x, y1 = wa.y * xa.y,
                        y2 = wa.z * xa.z, y3 = wa.w * xa.w;
            const float z0 = wb.x * xb.x, z1 = wb.y * xb.y,
                        z2 = wb.z * xb.z, z3 = wb.w * xb.w;
            dot = ce_a.x * y0 + ce_a.y * y1 + ce_a.z * y2 + ce_a.w * y3
                + ce_b.x * z0 + ce_b.y * z1 + ce_b.z * z2 + ce_b.w * z3;
            nr  = y0 * y0 + y1 * y1 + y2 * y2 + y3 * y3
                + z0 * z0 + z1 * z1 + z2 * z2 + z3 * z3;
        }
        #pragma unroll
        for (int o = 16; o > 0; o >>= 1) {
            dot += __shfl_xor_sync(0xffffffffu, dot, o);
            nr  += __shfl_xor_sync(0xffffffffu, nr, o);
        }
        if (lane == 0)
            s_sim[k] = dot / (cenorm * fmaxf(sqrtf(nr), EPSV));
    }
    __syncthreads();

    // softmax over 48 sims (warp 0)
    if (wid == 0) {
        const float s0 = s_sim[lane];
        const float s1 = (lane < KT - 32) ? s_sim[lane + 32] : -1e30f;
        float m = fmaxf(s0, s1);
        #pragma unroll
        for (int o = 16; o > 0; o >>= 1) m = fmaxf(m, __shfl_xor_sync(0xffffffffu, m, o));
        const float e0 = __expf(s0 - m);
        const float e1 = (lane < KT - 32) ? __expf(s1 - m) : 0.f;
        float ss = e0 + e1;
        #pragma unroll
        for (int o = 16; o > 0; o >>= 1) ss += __shfl_xor_sync(0xffffffffu, ss, o);
        const float inv = 1.f / ss;
        s_w[lane] = e0 * inv;
        if (lane < KT - 32) s_w[lane + 32] = e1 * inv;
    }
    __syncthreads();

    // Weighted sum of RAW rows per hop group, then apply w_n/w_n2 once.
    float acc1 = 0.f, acc2 = 0.f;
    #pragma unroll
    for (int k = 0; k < K1N; k++) acc1 += s_w[k] * s_raw[k * HD + tid];
    #pragma unroll
    for (int k = K1N; k < KT; k++) acc2 += s_w[k] * s_raw[k * HD + tid];
    g_inputs[(long)n * HD + tid] = wn * acc1 + wn2v * acc2 + ce;
    g_ce[(long)n * HD + tid] = ce;
}

// ---------------- K23: fused adapter ----------------
// Phase 1: hidden = elu(inputs[32xHD] @ W1 + b1)  (kept in smem, transposed)
// Phase 2: rawret = hidden @ W2 + b2 + ce, class sums via smem atomics.
__global__ __launch_bounds__(128) void k23_fused(
    const float* __restrict__ W1, const float* __restrict__ b1,
    const float* __restrict__ W2, const float* __restrict__ b2,
    const int* __restrict__ labels)
{
    __shared__ float s_At[32 * 36];    // phase1 A chunk [k][m], pad 36
    __shared__ float s_B[64 * 64];     // W1 chunk (32x64) / W2 chunk (64x64)
    __shared__ float s_ht[64 * 36];    // hidden transposed [k=64][m], pad 36
    __shared__ float s_cls[CC * 64];   // per-block per-chunk class partials
    const int tid = threadIdx.x;
    const int tx = tid & 15, ty = tid >> 4;   // ty 0..7
    const int row0 = blockIdx.x * 32;

    for (int i = tid; i < CC * 64; i += 128) s_cls[i] = 0.f;

    // ---- phase 1: 32xHD @ HDx64 ----
    float acc[4][4] = {};
    for (int kk = 0; kk < HD; kk += 32) {
        {
            const int kq = tid & 7;      // float4 slot
            const int m  = tid >> 3;     // 0..15
            #pragma unroll
            for (int p = 0; p < 2; p++) {
                const int mm = m + p * 16;
                const int row = row0 + mm;
                float4 a = (row < NN)
                    ? *(const float4*)(g_inputs + (long)row * HD + kk + kq * 4)
                    : make_float4(0.f, 0.f, 0.f, 0.f);
                s_At[(kq * 4 + 0) * 36 + mm] = a.x;
                s_At[(kq * 4 + 1) * 36 + mm] = a.y;
                s_At[(kq * 4 + 2) * 36 + mm] = a.z;
                s_At[(kq * 4 + 3) * 36 + mm] = a.w;
            }
        }
        {
            const int b = tid & 63;
            const int kb = tid >> 6;     // 0..1
            #pragma unroll
            for (int p = 0; p < 16; p++) {
                const int k = kb + p * 2;
                s_B[k * 64 + b] = W1[(kk + k) * BB + b];
            }
        }
        __syncthreads();
        #pragma unroll
        for (int k = 0; k < 32; k++) {
            const float4 a4 = *(const float4*)(s_At + k * 36 + ty * 4);
            const float4 b4 = *(const float4*)(s_B + k * 64 + tx * 4);
            acc[0][0] += a4.x * b4.x; acc[0][1] += a4.x * b4.y; acc[0][2] += a4.x * b4.z; acc[0][3] += a4.x * b4.w;
            acc[1][0] += a4.y * b4.x; acc[1][1] += a4.y * b4.y; acc[1][2] += a4.y * b4.z; acc[1][3] += a4.y * b4.w;
            acc[2][0] += a4.z * b4.x; acc[2][1] += a4.z * b4.y; acc[2][2] += a4.z * b4.z; acc[2][3] += a4.z * b4.w;
            acc[3][0] += a4.w * b4.x; acc[3][1] += a4.w * b4.y; acc[3][2] += a4.w * b4.z; acc[3][3] += a4.w * b4.w;
        }
        __syncthreads();
    }
    // elu + stash hidden transposed in smem: s_ht[col][m]
    #pragma unroll
    for (int i = 0; i < 4; i++) {
        const int mm = ty * 4 + i;
        #pragma unroll
        for (int j = 0; j < 4; j++) {
            const int col = tx * 4 + j;
            float vv = acc[i][j] + b1[col];
            vv = (vv > 0.f) ? vv : expm1f(vv);   // elu
            s_ht[col * 36 + mm] = vv;
        }
    }
    __syncthreads();

    // ---- phase 2: 32x64 @ 64xHD in 4 col-chunks ----
    for (int ccn = 0; ccn < 4; ccn++) {
        const int col0 = ccn * 64;
        {   // load W2 chunk [64][64]
            const int c = tid & 63;
            const int kb = tid >> 6;     // 0..1
            #pragma unroll
            for (int p = 0; p < 32; p++) {
                const int k = kb + p * 2;
                s_B[k * 64 + c] = W2[k * HD + col0 + c];
            }
        }
        __syncthreads();

        float a2[4][4] = {};
        #pragma unroll
        for (int k = 0; k < 64; k++) {
            const float4 a4 = *(const float4*)(s_ht + k * 36 + ty * 4);
            const float4 b4 = *(const float4*)(s_B + k * 64 + tx * 4);
            a2[0][0] += a4.x * b4.x; a2[0][1] += a4.x * b4.y; a2[0][2] += a4.x * b4.z; a2[0][3] += a4.x * b4.w;
            a2[1][0] += a4.y * b4.x; a2[1][1] += a4.y * b4.y; a2[1][2] += a4.y * b4.z; a2[1][3] += a4.y * b4.w;
            a2[2][0] += a4.z * b4.x; a2[2][1] += a4.z * b4.y; a2[2][2] += a4.z * b4.z; a2[2][3] += a4.z * b4.w;
            a2[3][0] += a4.w * b4.x; a2[3][1] += a4.w * b4.y; a2[3][2] += a4.w * b4.z; a2[3][3] += a4.w * b4.w;
        }

        #pragma unroll
        for (int i = 0; i < 4; i++) {
            const int row = row0 + ty * 4 + i;
            if (row >= NN) continue;
            const int lb = labels[row];
            #pragma unroll
            for (int j = 0; j < 4; j++) {
                const int cl = tx * 4 + j;
                const int gcol = col0 + cl;
                const float vv = a2[i][j] + b2[gcol] + g_ce[(long)row * HD + gcol];
                g_rawret[(long)row * HD + gcol] = vv;
                atomicAdd(&s_cls[lb * 64 + cl], vv);
            }
        }
        __syncthreads();
        for (int i = tid; i < CC * 64; i += 128) {
            atomicAdd(&g_clsum[(i >> 6) * HD + col0 + (i & 63)], s_cls[i]);
            s_cls[i] = 0.f;
        }
        __syncthreads();
    }
}

// ---------------- K5: per-node cos vs 7 class means + softmax (folds k4) ---------
__global__ __launch_bounds__(256) void k5_out(float* __restrict__ out) {
    __shared__ float s_ave[CC * HD];
    __shared__ float s_an[CC];
    const int tid = threadIdx.x, lane = tid & 31, wid = tid >> 5;
    for (int i = tid; i < CC * HD; i += 256)
        s_ave[i] = g_clsum[i] * (1.0f / PER_CLASS);
    __syncthreads();
    // warp w computes class w's clamped norm (w < CC)
    if (wid < CC) {
        float v = 0.f;
        #pragma unroll
        for (int t = 0; t < HD / 32; t++) {
            const float a = s_ave[wid * HD + lane + 32 * t];
            v += a * a;
        }
        #pragma unroll
        for (int o = 16; o > 0; o >>= 1) v += __shfl_xor_sync(0xffffffffu, v, o);
        if (lane == 0) s_an[wid] = fmaxf(sqrtf(v), EPSV);
    }
    __syncthreads();

    const int n = blockIdx.x * 8 + wid;   // grid = NN/8 exactly
    const float4* r = (const float4*)(g_rawret + (long)n * HD);
    const float4 x0 = r[lane], x1 = r[lane + 32];
    float nrm = x0.x * x0.x + x0.y * x0.y + x0.z * x0.z + x0.w * x0.w
              + x1.x * x1.x + x1.y * x1.y + x1.z * x1.z + x1.w * x1.w;
    float d[CC];
    #pragma unroll
    for (int c = 0; c < CC; c++) {
        const float4* av = (const float4*)(s_ave + c * HD);
        const float4 a0 = av[lane], a1 = av[lane + 32];
        d[c] = x0.x * a0.x + x0.y * a0.y + x0.z * a0.z + x0.w * a0.w
             + x1.x * a1.x + x1.y * a1.y + x1.z * a1.z + x1.w * a1.w;
    }
    #pragma unroll
    for (int o = 16; o > 0; o >>= 1) {
        nrm += __shfl_xor_sync(0xffffffffu, nrm, o);
        #pragma unroll
        for (int c = 0; c < CC; c++) d[c] += __shfl_xor_sync(0xffffffffu, d[c], o);
    }
    const float rn = fmaxf(sqrtf(nrm), EPSV);
    float mx = -1e30f;
    float sim[CC];
    #pragma unroll
    for (int c = 0; c < CC; c++) {
        sim[c] = d[c] / (rn * s_an[c]);
        mx = fmaxf(mx, sim[c]);
    }
    float sum = 0.f;
    #pragma unroll
    for (int c = 0; c < CC; c++) { sim[c] = __expf(sim[c] - mx); sum += sim[c]; }
    const float inv = 1.f / sum;
    #pragma unroll
    for (int c = 0; c < CC; c++)
        if (lane == c) out[n * CC + c] = sim[c] * inv;
}

// ---------------- launch ----------------
#define SMEM_K1 ((KT * HD + 3 * HD + 2 * KT + 8) * 4)

extern "C" void kernel_launch(void* const* d_in, const int* in_sizes, int n_in,
                              void* d_out, int out_size)
{
    const float* embeds = (const float*)d_in[0];
    const float* w_self = (const float*)d_in[1];
    const float* w_n    = (const float*)d_in[2];
    const float* w_n2   = (const float*)d_in[3];
    const float* W1     = (const float*)d_in[4];
    const float* b1     = (const float*)d_in[5];
    const float* W2     = (const float*)d_in[6];
    const float* b2     = (const float*)d_in[7];
    const int* idx      = (const int*)d_in[8];
    const int* nbr      = (const int*)d_in[9];
    const int* nbr2     = (const int*)d_in[10];
    const int* labels   = (const int*)d_in[11];
    float* out = (float*)d_out;

    cudaFuncSetAttribute(k1_attn, cudaFuncAttributeMaxDynamicSharedMemorySize, SMEM_K1);

    k1_attn<<<NN, 256, SMEM_K1>>>(embeds, w_self, w_n, w_n2, idx, nbr, nbr2);
    k23_fused<<<(NN + 31) / 32, 128>>>(W1, b1, W2, b2, labels);
    k5_out<<<NN / 8, 256>>>(out);
}